// round 13
// baseline (speedup 1.0000x reference)
#include <cuda_runtime.h>

#define N_NODES 50000
#define N_EDGES 600000
#define H 128

// ---------------- scratch (device globals; no allocation allowed) ----------
__device__ float4 g_mean4[(size_t)N_NODES * H / 4]; // mean-aggregated features
__device__ float4 g_h14[(size_t)N_NODES * H / 4];   // layer-1 output
__device__ float4 g_h24[(size_t)N_NODES * H / 4];   // layer-2 output

// CSR scratch (rebuilt every call; graph identical across layers)
__device__ int g_deg[N_NODES];
__device__ int g_fill[N_NODES];
__device__ int g_row_start[N_NODES + 1];
__device__ int g_edge_src[N_EDGES];
__device__ int g_is64;                              // edge dtype flag

// ---------------- edge-index access (dtype-robust) ---------------------------
// JAX's default config disables x64: edge_index declared int64 in the reference
// is almost certainly materialized as int32. Detect the layout on device:
// int64 little-endian with values < 2^31 => every odd 32-bit word is zero.
__global__ void detect_kernel(const int* __restrict__ ei32) {
    if (blockIdx.x == 0 && threadIdx.x == 0) {
        int is64 = 1;
        for (int i = 1; i < 64; i += 2)
            if (ei32[i] != 0) { is64 = 0; break; }
        g_is64 = is64;
    }
}

__device__ __forceinline__ int load_idx(const int* __restrict__ ei32,
                                        int is64, int elem) {
    int v = is64 ? ei32[(size_t)elem * 2] : ei32[elem];
    return ((unsigned)v < (unsigned)N_NODES) ? v : 0;   // safety mask
}

// ---------------- CSR build --------------------------------------------------
__global__ void zero_csr_kernel() {
    int i = blockIdx.x * blockDim.x + threadIdx.x;
    if (i < N_NODES) { g_deg[i] = 0; g_fill[i] = 0; }
}

__global__ void hist_kernel(const int* __restrict__ ei32) {
    int e = blockIdx.x * blockDim.x + threadIdx.x;
    if (e >= N_EDGES) return;
    int is64 = g_is64;
    int dst = load_idx(ei32, is64, N_EDGES + e);
    atomicAdd(&g_deg[dst], 1);
}

// single-block exclusive scan over 50000 degrees (1024 threads x 49 chunk)
__global__ __launch_bounds__(1024)
void scan_kernel() {
    __shared__ int partial[1024];
    const int CH = (N_NODES + 1023) / 1024;   // 49
    int t = threadIdx.x;
    int base = t * CH;
    int s = 0;
    for (int i = 0; i < CH; i++) {
        int idx = base + i;
        if (idx < N_NODES) s += g_deg[idx];
    }
    partial[t] = s;
    __syncthreads();
    if (t == 0) {
        int run = 0;
        for (int i = 0; i < 1024; i++) { int v = partial[i]; partial[i] = run; run += v; }
    }
    __syncthreads();
    int run = partial[t];
    for (int i = 0; i < CH; i++) {
        int idx = base + i;
        if (idx < N_NODES) { g_row_start[idx] = run; run += g_deg[idx]; }
    }
    if (t == 0) g_row_start[N_NODES] = N_EDGES;
}

__global__ void fill_kernel(const int* __restrict__ ei32) {
    int e = blockIdx.x * blockDim.x + threadIdx.x;
    if (e >= N_EDGES) return;
    int is64 = g_is64;
    int dst = load_idx(ei32, is64, N_EDGES + e);
    int src = load_idx(ei32, is64, e);
    int pos = g_row_start[dst] + atomicAdd(&g_fill[dst], 1);
    g_edge_src[pos] = src;
}

// ---------------- input selection (device-side; no host symbol APIs) --------
__device__ __forceinline__ const float4* sel_in4(int s, const float4* x4) {
    return (s == 0) ? x4 : (s == 1) ? g_h14 : g_h24;
}
__device__ __forceinline__ float* sel_out(int s, float* o) {
    return (s == 1) ? (float*)g_h14 : (s == 2) ? (float*)g_h24 : o;
}

// ---------------- gather: mean[n] = (1/max(deg,1)) * sum_{src in N(n)} h[src]
// one warp per node; 32 lanes x float4 = 128 features; no float atomics.
__global__ __launch_bounds__(256)
void gather_mean_kernel(const float* __restrict__ x, int in_sel) {
    int node = blockIdx.x * (blockDim.x >> 5) + (threadIdx.x >> 5);
    int lane = threadIdx.x & 31;
    if (node >= N_NODES) return;

    const float4* __restrict__ h4 = sel_in4(in_sel, (const float4*)x);

    int s = g_row_start[node];
    int e = g_row_start[node + 1];

    float4 acc0 = make_float4(0.f, 0.f, 0.f, 0.f);
    float4 acc1 = make_float4(0.f, 0.f, 0.f, 0.f);
    int i = s;
    for (; i + 1 < e; i += 2) {                 // 2-way MLP
        int s0 = g_edge_src[i];
        int s1 = g_edge_src[i + 1];
        float4 v0 = h4[(size_t)s0 * (H / 4) + lane];
        float4 v1 = h4[(size_t)s1 * (H / 4) + lane];
        acc0.x += v0.x; acc0.y += v0.y; acc0.z += v0.z; acc0.w += v0.w;
        acc1.x += v1.x; acc1.y += v1.y; acc1.z += v1.z; acc1.w += v1.w;
    }
    if (i < e) {
        int s0 = g_edge_src[i];
        float4 v0 = h4[(size_t)s0 * (H / 4) + lane];
        acc0.x += v0.x; acc0.y += v0.y; acc0.z += v0.z; acc0.w += v0.w;
    }
    float inv = 1.0f / fmaxf((float)(e - s), 1.0f);
    float4 m;
    m.x = (acc0.x + acc1.x) * inv;
    m.y = (acc0.y + acc1.y) * inv;
    m.z = (acc0.z + acc1.z) * inv;
    m.w = (acc0.w + acc1.w) * inv;
    g_mean4[(size_t)node * (H / 4) + lane] = m;
}

// ---------------- fused SAGE GEMM -------------------------------------------
// out[i][j] = sum_k mean[i][k]*Wl[j][k] + sum_k h[i][k]*Wr[j][k] + b[j]
// One K=256 GEMM: A=[mean | h] (64 rows/block), B=[Wl ; Wr] (128 rows).
// Block 256 threads (16x16), micro-tile 4 nodes x 8 cols per thread.
#define TM 64
#define KC 32
#define KPAD (KC + 4)   // stride 36 floats: f4-store conflict-free, <=2-way LDS

__global__ __launch_bounds__(256)
void sage_gemm_kernel(const float* __restrict__ x,
                      const float* __restrict__ Wl,
                      const float* __restrict__ Wr,
                      const float* __restrict__ bias,
                      float* __restrict__ dout,
                      int in_sel, int out_sel, int relu) {
    __shared__ float As[TM][KPAD];
    __shared__ float Bs[H][KPAD];

    const float4* __restrict__ hin4 = sel_in4(in_sel, (const float4*)x);
    float* __restrict__ out         = sel_out(out_sel, dout);

    int tx = threadIdx.x & 15;
    int ty = threadIdx.x >> 4;
    int node0 = blockIdx.x * TM;

    float acc[4][8];
#pragma unroll
    for (int u = 0; u < 8; u++) {
        float bj = bias[tx + 16 * u];
#pragma unroll
        for (int m = 0; m < 4; m++) acc[m][u] = bj;
    }

    for (int kc = 0; kc < 256 / KC; kc++) {
        int kg0 = kc * KC;

        // A tile: 64 rows x KC cols (mean for kg<128, h for kg>=128)
#pragma unroll
        for (int r = 0; r < (TM * KC / 4) / 256; r++) {
            int idx = threadIdx.x + r * 256;       // float4 index
            int i   = idx >> 3;                    // KC/4 = 8 f4 per row
            int kv  = idx & 7;
            int gi  = node0 + i;
            int kg  = kg0 + kv * 4;
            float4 v = make_float4(0.f, 0.f, 0.f, 0.f);
            if (gi < N_NODES) {
                if (kg < H)
                    v = g_mean4[(size_t)gi * (H / 4) + (kg >> 2)];
                else
                    v = hin4[(size_t)gi * (H / 4) + ((kg - H) >> 2)];
            }
            *(float4*)&As[i][kv * 4] = v;
        }
        // B tile: 128 rows x KC cols (Wl for kg<128, Wr for kg>=128)
#pragma unroll
        for (int r = 0; r < (H * KC / 4) / 256; r++) {
            int idx = threadIdx.x + r * 256;
            int j   = idx >> 3;
            int kv  = idx & 7;
            int kg  = kg0 + kv * 4;
            const float* W = (kg < H) ? Wl : Wr;
            int kk = (kg < H) ? kg : (kg - H);
            float4 v = ((const float4*)(W + (size_t)j * H))[kk >> 2];
            *(float4*)&Bs[j][kv * 4] = v;
        }
        __syncthreads();

#pragma unroll
        for (int k = 0; k < KC; k++) {
            float a[4], bb[8];
#pragma unroll
            for (int m = 0; m < 4; m++) a[m] = As[ty * 4 + m][k];
#pragma unroll
            for (int u = 0; u < 8; u++) bb[u] = Bs[tx + 16 * u][k];
#pragma unroll
            for (int m = 0; m < 4; m++)
#pragma unroll
                for (int u = 0; u < 8; u++)
                    acc[m][u] = fmaf(a[m], bb[u], acc[m][u]);
        }
        __syncthreads();
    }

#pragma unroll
    for (int m = 0; m < 4; m++) {
        int gi = node0 + ty * 4 + m;
        if (gi < N_NODES) {
#pragma unroll
            for (int u = 0; u < 8; u++) {
                float v = acc[m][u];
                if (relu) v = fmaxf(v, 0.0f);
                out[(size_t)gi * H + tx + 16 * u] = v;
            }
        }
    }
}

// ---------------- launcher ---------------------------------------------------
extern "C" void kernel_launch(void* const* d_in, const int* in_sizes, int n_in,
                              void* d_out, int out_size) {
    const float* x    = (const float*)d_in[0];
    const int*   ei32 = (const int*)d_in[1];   // dtype auto-detected on device
    const float* Wl1 = (const float*)d_in[2];
    const float* Wr1 = (const float*)d_in[3];
    const float* b1  = (const float*)d_in[4];
    const float* Wl2 = (const float*)d_in[5];
    const float* Wr2 = (const float*)d_in[6];
    const float* b2  = (const float*)d_in[7];
    const float* Wl3 = (const float*)d_in[8];
    const float* Wr3 = (const float*)d_in[9];
    const float* b3  = (const float*)d_in[10];
    float* out = (float*)d_out;

    const int NODE_BLKS  = (N_NODES + 255) / 256;        // 196
    const int EDGE_BLKS  = (N_EDGES + 255) / 256;        // 2344
    const int GATH_BLKS  = (N_NODES + 7) / 8;            // 6250 (8 warps/block)
    const int GEMM_BLKS  = (N_NODES + TM - 1) / TM;      // 782

    // ---- CSR build (once; graph identical for all 3 layers) ----
    detect_kernel<<<1, 32>>>(ei32);
    zero_csr_kernel<<<NODE_BLKS, 256>>>();
    hist_kernel<<<EDGE_BLKS, 256>>>(ei32);
    scan_kernel<<<1, 1024>>>();
    fill_kernel<<<EDGE_BLKS, 256>>>(ei32);

    // ---- layer 1 (relu) ----
    gather_mean_kernel<<<GATH_BLKS, 256>>>(x, /*in_sel=*/0);
    sage_gemm_kernel<<<GEMM_BLKS, 256>>>(x, Wl1, Wr1, b1, out,
                                         /*in=*/0, /*out=*/1, /*relu=*/1);
    // ---- layer 2 ----
    gather_mean_kernel<<<GATH_BLKS, 256>>>(x, /*in_sel=*/1);
    sage_gemm_kernel<<<GEMM_BLKS, 256>>>(x, Wl2, Wr2, b2, out,
                                         /*in=*/1, /*out=*/2, /*relu=*/0);
    // ---- layer 3 (writes d_out) ----
    gather_mean_kernel<<<GATH_BLKS, 256>>>(x, /*in_sel=*/2);
    sage_gemm_kernel<<<GEMM_BLKS, 256>>>(x, Wl3, Wr3, b3, out,
                                         /*in=*/2, /*out=*/0, /*relu=*/0);
}